// round 1
// baseline (speedup 1.0000x reference)
#include <cuda_runtime.h>
#include <math.h>

#define HW (768 * 768)
#define SPTS 8192
#define NCHUNK 8
#define CHUNK (SPTS / NCHUNK)   // 1024

// g_acc: 0 mask_sum, 1 normal_sq, 2 den, 3 num, 4 bce, 5 eik, 6 sdf,
//        7 con, 8 vis_total, 9 derr_sum, 10 pc_sum_xy, 11 pc_sum_yx
__device__ double g_acc[12];
__device__ float g_partial[2 * SPTS * NCHUNK];   // per-(src,chunk) min of (|x|^2 + score)

__device__ __forceinline__ float warpSum(float v) {
    #pragma unroll
    for (int o = 16; o; o >>= 1) v += __shfl_xor_sync(0xffffffffu, v, o);
    return v;
}

__global__ void k_init() {
    if (threadIdx.x < 12) g_acc[threadIdx.x] = 0.0;
}

// ---------------------------------------------------------------------------
// Pass 1: image reductions + eikonal + sdf + consistency
// ---------------------------------------------------------------------------
__global__ void k_main(const float* __restrict__ npred, const float* __restrict__ ngt,
                       const float* __restrict__ dpred, const float* __restrict__ dgt,
                       const float* __restrict__ mask,  const float* __restrict__ comp,
                       const float* __restrict__ grad,  const float* __restrict__ sdf,
                       const float* __restrict__ nwa,   const float* __restrict__ vis,
                       const float* __restrict__ w, int N, int P, int C)
{
    const int tid = blockIdx.x * blockDim.x + threadIdx.x;
    const int stride = gridDim.x * blockDim.x;

    float s_mask = 0.f, s_nsq = 0.f, s_den = 0.f, s_num = 0.f, s_bce = 0.f;
    for (int i = tid; i < HW; i += stride) {
        float m = (mask[i] > 0.5f) ? 1.0f : 0.0f;
        s_mask += m;

        float e0 = npred[3 * i + 0] - ngt[3 * i + 0];
        float e1 = npred[3 * i + 1] - ngt[3 * i + 1];
        float e2 = npred[3 * i + 2] - ngt[3 * i + 2];
        s_nsq += m * fmaf(e0, e0, fmaf(e1, e1, e2 * e2));

        float vg = dgt[i] * m;
        float vp = dpred[i] * m;
        s_den = fmaf(vg, vg, s_den);
        s_num = fmaf(vg, vp, s_num);

        float c = comp[i];
        c = fminf(fmaxf(c, 1e-5f), 1.0f - 1e-5f);
        s_bce -= m * __logf(c) + (1.0f - m) * __logf(1.0f - c);
    }

    float s_eik = 0.f, s_sdf = 0.f;
    for (int i = tid; i < N; i += stride) {
        float g0 = grad[3 * i + 0], g1 = grad[3 * i + 1], g2 = grad[3 * i + 2];
        float gn = sqrtf(fmaf(g0, g0, fmaf(g1, g1, g2 * g2)));
        float d = gn - 1.0f;
        s_eik = fmaf(d, d, s_eik);
        s_sdf += fabsf(sdf[i]);
    }

    float s_con = 0.f, s_vis = 0.f;
    for (int p = tid; p < P; p += stride) {
        float wp = w[p];
        const float* np_ = nwa + (size_t)p * C * 3;
        const float* vp_ = vis + (size_t)p * C;
        float px = np_[0], py = np_[1], pz = np_[2], pv = vp_[0];
        for (int i = 1; i < C; i++) {
            float cx = np_[3 * i + 0], cy = np_[3 * i + 1], cz = np_[3 * i + 2];
            float cv = vp_[i];
            float dx = px - cx, dy = py - cy, dz = pz - cz;
            float mse = fmaf(dx, dx, fmaf(dy, dy, dz * dz));
            float vv = pv * cv;
            s_vis += vv;
            s_con = fmaf(mse * vv, wp, s_con);
            px = cx; py = cy; pz = cz; pv = cv;
        }
    }

    __shared__ float sh[9];
    if (threadIdx.x < 9) sh[threadIdx.x] = 0.f;
    __syncthreads();
    float vals[9] = {s_mask, s_nsq, s_den, s_num, s_bce, s_eik, s_sdf, s_con, s_vis};
    #pragma unroll
    for (int k = 0; k < 9; k++) {
        float r = warpSum(vals[k]);
        if ((threadIdx.x & 31) == 0) atomicAdd(&sh[k], r);
    }
    __syncthreads();
    if (threadIdx.x < 9) atomicAdd(&g_acc[threadIdx.x], (double)sh[threadIdx.x]);
}

// ---------------------------------------------------------------------------
// Chamfer: per (direction, src-block of 256, dst-chunk of 1024) partial min.
// score = |y|^2 - 2 x.y  (argmin-equivalent to squared distance); store |x|^2+min.
// ---------------------------------------------------------------------------
__global__ void __launch_bounds__(256) k_chamfer(const float* __restrict__ X,
                                                 const float* __restrict__ Y)
{
    const int b = blockIdx.x;
    const int dir = b >> 8;             // 32 src-blocks * 8 chunks = 256 per dir
    const int rem = b & 255;
    const int srcblk = rem >> 3;
    const int chunk = rem & 7;

    const float* __restrict__ src = dir == 0 ? X : Y;
    const float* __restrict__ dst = dir == 0 ? Y : X;

    __shared__ float4 sh[CHUNK];        // 16 KB: (y0, y1, y2, |y|^2)
    const int base = chunk * CHUNK;
    for (int i = threadIdx.x; i < CHUNK; i += 256) {
        float y0 = dst[3 * (base + i) + 0];
        float y1 = dst[3 * (base + i) + 1];
        float y2 = dst[3 * (base + i) + 2];
        sh[i] = make_float4(y0, y1, y2, fmaf(y0, y0, fmaf(y1, y1, y2 * y2)));
    }
    __syncthreads();

    const int s = srcblk * 256 + threadIdx.x;
    float x0 = src[3 * s + 0], x1 = src[3 * s + 1], x2 = src[3 * s + 2];
    float a0 = -2.0f * x0, a1 = -2.0f * x1, a2 = -2.0f * x2;
    float xx = fmaf(x0, x0, fmaf(x1, x1, x2 * x2));

    // two independent min chains to relax the FMNMX dependency
    float m0 = 3.0e38f, m1 = 3.0e38f;
    #pragma unroll 8
    for (int i = 0; i < CHUNK; i += 2) {
        float4 ya = sh[i];
        float4 yb = sh[i + 1];
        float sa = fmaf(a0, ya.x, fmaf(a1, ya.y, fmaf(a2, ya.z, ya.w)));
        float sb = fmaf(a0, yb.x, fmaf(a1, yb.y, fmaf(a2, yb.z, yb.w)));
        m0 = fminf(m0, sa);
        m1 = fminf(m1, sb);
    }
    g_partial[((dir << 13) + s) * NCHUNK + chunk] = xx + fminf(m0, m1);
}

// ---------------------------------------------------------------------------
// Pass 2: depth |vg*scale - vp| (needs den/num from pass 1) + chamfer reduce
// ---------------------------------------------------------------------------
__global__ void k_pass2(const float* __restrict__ dpred, const float* __restrict__ dgt,
                        const float* __restrict__ mask)
{
    const int tid = blockIdx.x * blockDim.x + threadIdx.x;
    const int stride = gridDim.x * blockDim.x;

    double den = g_acc[2], num = g_acc[3];
    float scale = (float)(num / den);
    if (!isfinite(scale)) scale = 1.0f;

    float s_derr = 0.f;
    for (int i = tid; i < HW; i += stride) {
        float m = (mask[i] > 0.5f) ? 1.0f : 0.0f;
        float vg = dgt[i] * m;
        float vp = dpred[i] * m;
        s_derr += fabsf(fmaf(vg, scale, -vp));
    }

    float s0 = 0.f, s1 = 0.f;
    for (int s = tid; s < 2 * SPTS; s += stride) {
        const float* p = &g_partial[s * NCHUNK];
        float mn = p[0];
        #pragma unroll
        for (int c = 1; c < NCHUNK; c++) mn = fminf(mn, p[c]);
        float d = sqrtf(fmaxf(mn, 0.0f));
        if (s < SPTS) s0 += d; else s1 += d;
    }

    __shared__ float sh[3];
    if (threadIdx.x < 3) sh[threadIdx.x] = 0.f;
    __syncthreads();
    float vals[3] = {s_derr, s0, s1};
    #pragma unroll
    for (int k = 0; k < 3; k++) {
        float r = warpSum(vals[k]);
        if ((threadIdx.x & 31) == 0) atomicAdd(&sh[k], r);
    }
    __syncthreads();
    if (threadIdx.x < 3) atomicAdd(&g_acc[9 + threadIdx.x], (double)sh[threadIdx.x]);
}

// ---------------------------------------------------------------------------
// Final combine
// ---------------------------------------------------------------------------
__global__ void k_final(float* __restrict__ out, int out_size, int N)
{
    double mask_sum = g_acc[0] + 1e-5;
    double normal_loss = g_acc[1] / mask_sum;

    double den = g_acc[2];
    double depth_loss = g_acc[9] / (mask_sum + 1e-8);
    if (den < 1e-10) depth_loss = 0.0;
    if (!isfinite(depth_loss)) depth_loss = 0.0;

    double pc = g_acc[10] / (double)SPTS + g_acc[11] / (double)SPTS;
    double bce = g_acc[4] / (double)HW;
    double eik = g_acc[5] / (double)N;
    double sdfl = g_acc[6] / (double)N;
    double con = (g_acc[8] > 0.0) ? g_acc[7] / g_acc[8] : 0.0;

    float loss = (float)(normal_loss + depth_loss + pc + bce + eik + sdfl + con);
    for (int i = 0; i < out_size; i++) out[i] = loss;
}

extern "C" void kernel_launch(void* const* d_in, const int* in_sizes, int n_in,
                              void* d_out, int out_size)
{
    const float* npred = (const float*)d_in[0];
    const float* ngt   = (const float*)d_in[1];
    const float* dpred = (const float*)d_in[2];
    const float* dgt   = (const float*)d_in[3];
    const float* X     = (const float*)d_in[4];
    const float* Y     = (const float*)d_in[5];
    const float* mask  = (const float*)d_in[6];
    const float* comp  = (const float*)d_in[7];
    const float* grad  = (const float*)d_in[8];
    const float* sdf   = (const float*)d_in[9];
    const float* nwa   = (const float*)d_in[10];
    const float* vis   = (const float*)d_in[11];
    const float* w     = (const float*)d_in[12];

    int N = in_sizes[9];                 // 100000
    int P = in_sizes[12];                // 50000
    int C = in_sizes[11] / P;            // 4

    k_init<<<1, 32>>>();
    k_main<<<592, 256>>>(npred, ngt, dpred, dgt, mask, comp, grad, sdf, nwa, vis, w, N, P, C);
    k_chamfer<<<2 * 32 * NCHUNK, 256>>>(X, Y);
    k_pass2<<<592, 256>>>(dpred, dgt, mask);
    k_final<<<1, 1>>>((float*)d_out, out_size, N);
}